// round 14
// baseline (speedup 1.0000x reference)
#include <cuda_runtime.h>
#include <cuda_fp16.h>
#include <math.h>
#include <stdint.h>

// ---------------- problem constants ----------------
#define B_      1024
#define NTOK    54
#define WIN     49
#define NP      5
#define NH      12
#define HD      32
#define DIM     384
#define QKVD    1152
#define NWIN    64
#define WH      7
#define WW      7
#define SCALE   0.17677669529663687f
#define MTOK    (B_*NTOK)       // 55296
#define KDIM    384

// ---------------- scratch ----------------
__device__ __half d_qkv[(size_t)MTOK * QKVD];    // fp16 qkv
__device__ __half d_att[(size_t)MTOK * DIM];     // fp16 attention output
__device__ __half d_xh[(size_t)MTOK * DIM];      // fp16 x
__device__ __half d_wqh[QKVD * DIM];             // fp16 qkv_w
__device__ __half d_wph[DIM * DIM];              // fp16 proj_w
__device__ __half d_bmh[NH * NWIN * 64 * 64];    // combined bias+mask, fp16

// ---------------- prepass: convert all three arrays to fp16 (one kernel) --
#define PN1 (MTOK * DIM / 4)
#define PN2 (QKVD * DIM / 4)
#define PN3 (DIM * DIM / 4)

__global__ void prep_all(const float* __restrict__ x,
                         const float* __restrict__ qw,
                         const float* __restrict__ pw)
{
    int i = blockIdx.x * blockDim.x + threadIdx.x;
    const float* in;
    __half* out;
    int j;
    if (i < PN1)              { in = x;  out = d_xh;  j = i; }
    else if (i < PN1 + PN2)   { in = qw; out = d_wqh; j = i - PN1; }
    else if (i < PN1 + PN2 + PN3) { in = pw; out = d_wph; j = i - PN1 - PN2; }
    else return;
    float4 v = reinterpret_cast<const float4*>(in)[j];
    reinterpret_cast<__half2*>(out)[j * 2]     = __floats2half2_rn(v.x, v.y);
    reinterpret_cast<__half2*>(out)[j * 2 + 1] = __floats2half2_rn(v.z, v.w);
}

// ---------------- prepass: combined bias+mask (one thread per (w,r,c)) ----
__global__ void bm_kernel(const float* __restrict__ rpb, const float* __restrict__ mask) {
    int idx = blockIdx.x * blockDim.x + threadIdx.x;
    if (idx >= NWIN * 64 * 64) return;
    const int c  = idx & 63;
    const int r  = (idx >> 6) & 63;
    const int wv = idx >> 12;
    const int pos = (wv << 12) + (r << 6) + c;

    if (r >= NTOK) {
        #pragma unroll
        for (int h = 0; h < NH; h++)
            d_bmh[(h * NWIN << 12) + pos] = __float2half_rn(0.f);
        return;
    }
    if (c >= NTOK) {
        #pragma unroll
        for (int h = 0; h < NH; h++)
            d_bmh[(h * NWIN << 12) + pos] = __float2half_rn(-60000.f);
        return;
    }
    if (r < NP || c < NP) {
        #pragma unroll
        for (int h = 0; h < NH; h++)
            d_bmh[(h * NWIN << 12) + pos] = __float2half_rn(0.f);
        return;
    }
    const int i = r - NP, j = c - NP;
    const int ih = i / WW, iw = i % WW;
    const int jh = j / WW, jw = j % WW;
    const int rpi = (ih - jh + WH - 1) * (2 * WW - 1) + (iw - jw + WW - 1);
    const float m = mask[wv * WIN * WIN + i * WIN + j];
    #pragma unroll
    for (int h = 0; h < NH; h++)
        d_bmh[(h * NWIN << 12) + pos] = __float2half_rn(rpb[rpi * NH + h] + m);
}

// ================= shared MMA/ldmatrix helpers =================
__device__ __forceinline__ void cp16(uint32_t smem, const __half* g) {
    asm volatile("cp.async.cg.shared.global [%0], [%1], 16;\n" :: "r"(smem), "l"(g));
}

__device__ __forceinline__ void ldsm_x4(uint32_t* r, uint32_t addr) {
    asm volatile("ldmatrix.sync.aligned.m8n8.x4.shared.b16 {%0,%1,%2,%3}, [%4];"
        : "=r"(r[0]), "=r"(r[1]), "=r"(r[2]), "=r"(r[3]) : "r"(addr));
}

__device__ __forceinline__ void ldsm_x4_t(uint32_t* r, uint32_t addr) {
    asm volatile("ldmatrix.sync.aligned.m8n8.x4.trans.shared.b16 {%0,%1,%2,%3}, [%4];"
        : "=r"(r[0]), "=r"(r[1]), "=r"(r[2]), "=r"(r[3]) : "r"(addr));
}

__device__ __forceinline__ void mma_f16(float* c, const uint32_t* a,
                                        uint32_t b0, uint32_t b1)
{
    asm volatile(
        "mma.sync.aligned.m16n8k16.row.col.f32.f16.f16.f32 "
        "{%0,%1,%2,%3}, {%4,%5,%6,%7}, {%8,%9}, {%0,%1,%2,%3};\n"
        : "+f"(c[0]), "+f"(c[1]), "+f"(c[2]), "+f"(c[3])
        : "r"(a[0]), "r"(a[1]), "r"(a[2]), "r"(a[3]), "r"(b0), "r"(b1));
}

// ================= fp16 mma.sync GEMM, BK=64, ldmatrix, 3-stage ==========
#define BM 128
#define BN 128
#define BK 64                      // k-elements (halfs) per tile
#define RS 72                      // row stride in halfs (144 B) -> conflict-free LDSM
#define ABYTES  (BM * RS * 2)      // 18432
#define STAGEB  (2 * ABYTES)       // 36864 (A + B per stage)
#define SMEM_GEMM (3 * STAGEB)     // 110592

template<int N, bool HOUT>
__device__ __forceinline__ void tgemm_body(
    const __half* __restrict__ A, const __half* __restrict__ W,
    const float* __restrict__ bias, void* Cv, int K)
{
    extern __shared__ __align__(16) char smem[];

    const int tid  = threadIdx.x;
    const int warp = tid >> 5, lane = tid & 31;
    const int g    = lane >> 2, tg = lane & 3;
    const int wm   = warp & 1;
    const int wn   = warp >> 1;
    const int m0   = blockIdx.y * BM;
    const int n0   = blockIdx.x * BN;

    // producer: row = tid/2, half-offset (tid&1)*32; 4 x 16B per matrix
    const int lr = tid >> 1;
    const int hk = (tid & 1) * 32;
    const __half* Ag = A + (size_t)(m0 + lr) * K + hk;
    const __half* Wg = W + (size_t)(n0 + lr) * K + hk;

    const uint32_t sbase = (uint32_t)__cvta_generic_to_shared(smem);
    const uint32_t poff  = (lr * RS + hk) * 2;

    const int l7  = lane & 7;
    const int lb3 = (lane >> 3) & 1;
    const int lb4 = lane >> 4;
    uint32_t aoffA[4], boffB[2];
    #pragma unroll
    for (int i = 0; i < 4; i++) {
        const int row = wm * 64 + i * 16 + l7 + 8 * lb3;
        aoffA[i] = (row * RS + 8 * lb4) * 2;
    }
    #pragma unroll
    for (int p = 0; p < 2; p++) {
        const int row = wn * 32 + p * 16 + l7 + 8 * lb4;
        boffB[p] = (row * RS + 8 * lb3) * 2;
    }

    float acc[4][4][4];
    #pragma unroll
    for (int i = 0; i < 4; i++)
        #pragma unroll
        for (int j = 0; j < 4; j++)
            #pragma unroll
            for (int c = 0; c < 4; c++) acc[i][j][c] = 0.f;

    const int nt = K / BK;     // 6

    // prologue: stage tiles 0 and 1
    #pragma unroll
    for (int p = 0; p < 2; p++) {
        const __half* ap = Ag + (size_t)p * BK;
        const __half* wp = Wg + (size_t)p * BK;
        const uint32_t sA = sbase + p * STAGEB + poff;
        const uint32_t sB = sA + ABYTES;
        #pragma unroll
        for (int q = 0; q < 4; q++) {
            cp16(sA + q * 16, ap + q * 8);
            cp16(sB + q * 16, wp + q * 8);
        }
        asm volatile("cp.async.commit_group;\n");
    }

    int stage = 0;
    int nstage = 2;

    for (int t = 0; t < nt; t++) {
        if (t < nt - 1) asm volatile("cp.async.wait_group 1;\n");
        else            asm volatile("cp.async.wait_group 0;\n");
        __syncthreads();

        if (t + 2 < nt) {
            const __half* ap = Ag + (size_t)(t + 2) * BK;
            const __half* wp = Wg + (size_t)(t + 2) * BK;
            const uint32_t sA = sbase + nstage * STAGEB + poff;
            const uint32_t sB = sA + ABYTES;
            #pragma unroll
            for (int q = 0; q < 4; q++) {
                cp16(sA + q * 16, ap + q * 8);
                cp16(sB + q * 16, wp + q * 8);
            }
            asm volatile("cp.async.commit_group;\n");
        }

        const uint32_t aS = sbase + stage * STAGEB;
        const uint32_t bS = aS + ABYTES;

        #pragma unroll
        for (int s = 0; s < 4; s++) {
            const uint32_t ks = s * 32;          // 16 halfs = 32 bytes
            uint32_t af[4][4], bfr[4][2];
            #pragma unroll
            for (int i = 0; i < 4; i++)
                ldsm_x4(af[i], aS + aoffA[i] + ks);
            #pragma unroll
            for (int p = 0; p < 2; p++) {
                uint32_t br[4];
                ldsm_x4(br, bS + boffB[p] + ks);
                bfr[2 * p][0]     = br[0];  bfr[2 * p][1]     = br[1];
                bfr[2 * p + 1][0] = br[2];  bfr[2 * p + 1][1] = br[3];
            }
            #pragma unroll
            for (int i = 0; i < 4; i++)
                #pragma unroll
                for (int j = 0; j < 4; j++)
                    mma_f16(acc[i][j], af[i], bfr[j][0], bfr[j][1]);
        }

        stage  = (stage  == 2) ? 0 : stage  + 1;
        nstage = (nstage == 2) ? 0 : nstage + 1;
    }

    #pragma unroll
    for (int i = 0; i < 4; i++) {
        const int rb = m0 + wm * 64 + i * 16 + g;
        #pragma unroll
        for (int j = 0; j < 4; j++) {
            const int cb = n0 + wn * 32 + j * 8 + 2 * tg;
            const float b0v = bias[cb], b1v = bias[cb + 1];
            if (HOUT) {
                __half* C = (__half*)Cv;
                *reinterpret_cast<__half2*>(&C[(size_t)rb * N + cb]) =
                    __floats2half2_rn(acc[i][j][0] + b0v, acc[i][j][1] + b1v);
                *reinterpret_cast<__half2*>(&C[(size_t)(rb + 8) * N + cb]) =
                    __floats2half2_rn(acc[i][j][2] + b0v, acc[i][j][3] + b1v);
            } else {
                float* C = (float*)Cv;
                float2 v0, v1;
                v0.x = acc[i][j][0] + b0v;  v0.y = acc[i][j][1] + b1v;
                v1.x = acc[i][j][2] + b0v;  v1.y = acc[i][j][3] + b1v;
                *reinterpret_cast<float2*>(&C[(size_t)rb * N + cb])       = v0;
                *reinterpret_cast<float2*>(&C[(size_t)(rb + 8) * N + cb]) = v1;
            }
        }
    }
}

__global__ __launch_bounds__(256, 2) void k_qkv(const float* __restrict__ b)
{
    tgemm_body<QKVD, true>(d_xh, d_wqh, b, d_qkv, KDIM);
}

__global__ __launch_bounds__(256, 2) void k_proj(const float* __restrict__ b,
                                                 float* __restrict__ out)
{
    tgemm_body<DIM, false>(d_att, d_wph, b, out, KDIM);
}

// ================= fp16 attention: one block = 2 heads ========
#define UQKV 15360u
#define APPB 30720u
#define ATT_SMEM (30720 + 9216)    // 39936 B

__device__ __forceinline__ void attn_load(uint32_t sbuf, const __half* base, int tid) {
    for (int i = tid; i < 648; i += 128) {
        const int r   = i / 12;
        const int seg = (i % 12) / 4;
        const int ch  = i % 4;
        cp16(sbuf + seg * 5120 + r * 80 + ch * 16,
             base + r * QKVD + seg * DIM + ch * 8);
    }
    asm volatile("cp.async.commit_group;\n");
}

__device__ __forceinline__ void attn_unit(
    uint32_t sb, uint32_t qb, __half* smh, int b, int h, int tid)
{
    const int w = tid >> 5, lane = tid & 31;
    const int g = lane >> 2, tg = lane & 3;
    const int r0 = w * 16 + g;

    const int l7  = lane & 7;
    const int lb3 = (lane >> 3) & 1;
    const int lb4 = lane >> 4;

    const uint32_t aoffQ = ((w * 16 + l7 + 8 * lb3) * 40 + 8 * lb4) * 2;
    uint32_t boffK[4];
    #pragma unroll
    for (int j2 = 0; j2 < 4; j2++)
        boffK[j2] = ((j2 * 16 + l7 + 8 * lb4) * 40 + 8 * lb3) * 2;
    const uint32_t poffP = ((w * 16 + l7 + 8 * lb3) * 72 + 8 * lb4) * 2;
    const int g2 = lane >> 3;
    const uint32_t voffV = (((g2 & 1) * 8 + l7) * 40 + (g2 >> 1) * 8) * 2;

    // ---- QK^T ----
    float s[8][4];
    #pragma unroll
    for (int j = 0; j < 8; j++)
        #pragma unroll
        for (int c = 0; c < 4; c++) s[j][c] = 0.f;

    #pragma unroll
    for (int kc = 0; kc < 2; kc++) {
        const uint32_t ks = kc * 32;
        uint32_t aQ[4];
        ldsm_x4(aQ, qb + aoffQ + ks);
        #pragma unroll
        for (int j2 = 0; j2 < 4; j2++) {
            uint32_t bK[4];
            ldsm_x4(bK, qb + 5120 + boffK[j2] + ks);
            mma_f16(s[2 * j2],     aQ, bK[0], bK[1]);
            mma_f16(s[2 * j2 + 1], aQ, bK[2], bK[3]);
        }
    }

    // ---- scale + bias + mask ----
    const __half* bmp = d_bmh + ((size_t)(h * NWIN + (b & (NWIN - 1)))) * 64 * 64;
    #pragma unroll
    for (int j = 0; j < 8; j++) {
        const float2 t0 = __half22float2(
            *reinterpret_cast<const __half2*>(&bmp[r0 * 64 + j * 8 + 2 * tg]));
        const float2 t1 = __half22float2(
            *reinterpret_cast<const __half2*>(&bmp[(r0 + 8) * 64 + j * 8 + 2 * tg]));
        s[j][0] = s[j][0] * SCALE + t0.x;
        s[j][1] = s[j][1] * SCALE + t0.y;
        s[j][2] = s[j][2] * SCALE + t1.x;
        s[j][3] = s[j][3] * SCALE + t1.y;
    }

    // ---- softmax ----
    float m0 = -1e30f, m1 = -1e30f;
    #pragma unroll
    for (int j = 0; j < 8; j++) {
        m0 = fmaxf(m0, fmaxf(s[j][0], s[j][1]));
        m1 = fmaxf(m1, fmaxf(s[j][2], s[j][3]));
    }
    m0 = fmaxf(m0, __shfl_xor_sync(0xffffffffu, m0, 1));
    m0 = fmaxf(m0, __shfl_xor_sync(0xffffffffu, m0, 2));
    m1 = fmaxf(m1, __shfl_xor_sync(0xffffffffu, m1, 1));
    m1 = fmaxf(m1, __shfl_xor_sync(0xffffffffu, m1, 2));

    float sum0 = 0.f, sum1 = 0.f;
    #pragma unroll
    for (int j = 0; j < 8; j++) {
        s[j][0] = __expf(s[j][0] - m0);
        s[j][1] = __expf(s[j][1] - m0);
        s[j][2] = __expf(s[j][2] - m1);
        s[j][3] = __expf(s[j][3] - m1);
        sum0 += s[j][0] + s[j][1];
        sum1 += s[j][2] + s[j][3];
    }
    sum0 += __shfl_xor_sync(0xffffffffu, sum0, 1);
    sum0 += __shfl_xor_sync(0xffffffffu, sum0, 2);
    sum1 += __shfl_xor_sync(0xffffffffu, sum1, 1);
    sum1 += __shfl_xor_sync(0xffffffffu, sum1, 2);
    const float inv0 = 1.f / sum0;
    const float inv1 = 1.f / sum1;

    // ---- write P (fp16) — each warp writes/reads only its own 16 rows ----
    #pragma unroll
    for (int j = 0; j < 8; j++) {
        *reinterpret_cast<__half2*>(&smh[(APPB >> 1) + r0 * 72 + j * 8 + 2 * tg]) =
            __floats2half2_rn(s[j][0] * inv0, s[j][1] * inv0);
        *reinterpret_cast<__half2*>(&smh[(APPB >> 1) + (r0 + 8) * 72 + j * 8 + 2 * tg]) =
            __floats2half2_rn(s[j][2] * inv1, s[j][3] * inv1);
    }
    __syncwarp();

    // ---- PV (V via ldmatrix.trans) ----
    float o[4][4];
    #pragma unroll
    for (int n = 0; n < 4; n++)
        #pragma unroll
        for (int c = 0; c < 4; c++) o[n][c] = 0.f;

    #pragma unroll
    for (int kc = 0; kc < 4; kc++) {
        uint32_t aP[4];
        ldsm_x4(aP, sb + APPB + poffP + kc * 32);
        #pragma unroll
        for (int nh = 0; nh < 2; nh++) {
            uint32_t bV[4];
            ldsm_x4_t(bV, qb + 10240 + voffV + nh * 32 + kc * 1280);
            mma_f16(o[2 * nh],     aP, bV[0], bV[1]);
            mma_f16(o[2 * nh + 1], aP, bV[2], bV[3]);
        }
    }

    // ---- store fp16 for the proj GEMM ----
    if (r0 < NTOK) {
        __half* op = d_att + ((size_t)b * NTOK + r0) * DIM + h * HD;
        #pragma unroll
        for (int n = 0; n < 4; n++)
            *reinterpret_cast<__half2*>(&op[n * 8 + 2 * tg]) =
                __floats2half2_rn(o[n][0], o[n][1]);
    }
    if (r0 + 8 < NTOK) {
        __half* op = d_att + ((size_t)b * NTOK + r0 + 8) * DIM + h * HD;
        #pragma unroll
        for (int n = 0; n < 4; n++)
            *reinterpret_cast<__half2*>(&op[n * 8 + 2 * tg]) =
                __floats2half2_rn(o[n][2], o[n][3]);
    }
}

__global__ __launch_bounds__(128) void attn_tc()
{
    __shared__ __align__(16) char smraw[ATT_SMEM];
    __half* smh = reinterpret_cast<__half*>(smraw);
    const uint32_t sb = (uint32_t)__cvta_generic_to_shared(smraw);

    const int tid = threadIdx.x;
    const int u0  = blockIdx.x * 2;
    const int b   = u0 / NH;
    const int h0  = u0 % NH;

    const __half* base0 = d_qkv + (size_t)b * NTOK * QKVD + h0 * HD;
    const __half* base1 = base0 + HD;

    // zero pad rows 54..63 of Q,K,V in BOTH unit buffers
    for (int i = tid; i < 960; i += 128) {
        const int buf = i / 480;
        const int j   = i % 480;
        const int seg = j / 160;
        const int rr  = 54 + (j / 16) % 10;
        const int cw  = j % 16;
        reinterpret_cast<uint32_t*>(smraw)[(buf * UQKV + seg * 5120 + rr * 80) / 4 + cw] = 0;
    }

    attn_load(sb, base0, tid);            // group 1 (older)
    attn_load(sb + UQKV, base1, tid);     // group 0 (newer)

    asm volatile("cp.async.wait_group 1;\n");
    __syncthreads();
    attn_unit(sb, sb, smh, b, h0, tid);

    asm volatile("cp.async.wait_group 0;\n");
    __syncthreads();
    attn_unit(sb, sb + UQKV, smh, b, h0 + 1, tid);
}

// ---------------- launch ----------------
extern "C" void kernel_launch(void* const* d_in, const int* in_sizes, int n_in,
                              void* d_out, int out_size)
{
    const float* x      = (const float*)d_in[0];
    const float* mask   = (const float*)d_in[1];
    const float* qkv_w  = (const float*)d_in[2];
    const float* qkv_b  = (const float*)d_in[3];
    const float* proj_w = (const float*)d_in[4];
    const float* proj_b = (const float*)d_in[5];
    const float* rpb    = (const float*)d_in[6];
    float* out          = (float*)d_out;

    cudaFuncSetAttribute(k_qkv,  cudaFuncAttributeMaxDynamicSharedMemorySize, SMEM_GEMM);
    cudaFuncSetAttribute(k_proj, cudaFuncAttributeMaxDynamicSharedMemorySize, SMEM_GEMM);

    {
        const int total = PN1 + PN2 + PN3;
        prep_all<<<(total + 255) / 256, 256>>>(x, qkv_w, proj_w);
        bm_kernel<<<(NWIN * 64 * 64 + 255) / 256, 256>>>(rpb, mask);
    }

    {   // QKV: (55296 x 384) @ (1152 x 384)^T -> fp16
        dim3 grid(QKVD / BN, MTOK / BM);
        k_qkv<<<grid, 256, SMEM_GEMM>>>(qkv_b);
    }

    attn_tc<<<B_ * NH / 2, 128>>>();

    {   // proj: (55296 x 384) @ (384 x 384)^T -> fp32 out
        dim3 grid(DIM / BN, MTOK / BM);
        k_proj<<<grid, 256, SMEM_GEMM>>>(proj_b, out);
    }
}

// round 15
// speedup vs baseline: 1.1624x; 1.1624x over previous
#include <cuda_runtime.h>
#include <cuda_fp16.h>
#include <math.h>
#include <stdint.h>

// ---------------- problem constants ----------------
#define B_      1024
#define NTOK    54
#define WIN     49
#define NP      5
#define NH      12
#define HD      32
#define DIM     384
#define QKVD    1152
#define NWIN    64
#define WH      7
#define WW      7
#define SCALE   0.17677669529663687f
#define MTOK    (B_*NTOK)       // 55296
#define KDIM    384

// ---------------- scratch ----------------
__device__ __half d_qkv[(size_t)MTOK * QKVD];    // fp16 qkv
__device__ __half d_att[(size_t)MTOK * DIM];     // fp16 attention output
__device__ __half d_xh[(size_t)MTOK * DIM];      // fp16 x
__device__ __half d_wqh[QKVD * DIM];             // fp16 qkv_w
__device__ __half d_wph[DIM * DIM];              // fp16 proj_w
__device__ __half d_bmh[NH * NWIN * 64 * 64];    // combined bias+mask, fp16

// ---------------- prepass: convert all three arrays to fp16 (one kernel) --
#define PN1 (MTOK * DIM / 4)
#define PN2 (QKVD * DIM / 4)
#define PN3 (DIM * DIM / 4)

__global__ void prep_all(const float* __restrict__ x,
                         const float* __restrict__ qw,
                         const float* __restrict__ pw)
{
    int i = blockIdx.x * blockDim.x + threadIdx.x;
    const float* in;
    __half* out;
    int j;
    if (i < PN1)              { in = x;  out = d_xh;  j = i; }
    else if (i < PN1 + PN2)   { in = qw; out = d_wqh; j = i - PN1; }
    else if (i < PN1 + PN2 + PN3) { in = pw; out = d_wph; j = i - PN1 - PN2; }
    else return;
    float4 v = reinterpret_cast<const float4*>(in)[j];
    reinterpret_cast<__half2*>(out)[j * 2]     = __floats2half2_rn(v.x, v.y);
    reinterpret_cast<__half2*>(out)[j * 2 + 1] = __floats2half2_rn(v.z, v.w);
}

// ---------------- prepass: combined bias+mask (one thread per (w,r,c)) ----
__global__ void bm_kernel(const float* __restrict__ rpb, const float* __restrict__ mask) {
    int idx = blockIdx.x * blockDim.x + threadIdx.x;
    if (idx >= NWIN * 64 * 64) return;
    const int c  = idx & 63;
    const int r  = (idx >> 6) & 63;
    const int wv = idx >> 12;
    const int pos = (wv << 12) + (r << 6) + c;

    if (r >= NTOK) {
        #pragma unroll
        for (int h = 0; h < NH; h++)
            d_bmh[(h * NWIN << 12) + pos] = __float2half_rn(0.f);
        return;
    }
    if (c >= NTOK) {
        #pragma unroll
        for (int h = 0; h < NH; h++)
            d_bmh[(h * NWIN << 12) + pos] = __float2half_rn(-60000.f);
        return;
    }
    if (r < NP || c < NP) {
        #pragma unroll
        for (int h = 0; h < NH; h++)
            d_bmh[(h * NWIN << 12) + pos] = __float2half_rn(0.f);
        return;
    }
    const int i = r - NP, j = c - NP;
    const int ih = i / WW, iw = i % WW;
    const int jh = j / WW, jw = j % WW;
    const int rpi = (ih - jh + WH - 1) * (2 * WW - 1) + (iw - jw + WW - 1);
    const float m = mask[wv * WIN * WIN + i * WIN + j];
    #pragma unroll
    for (int h = 0; h < NH; h++)
        d_bmh[(h * NWIN << 12) + pos] = __float2half_rn(rpb[rpi * NH + h] + m);
}

// ================= shared MMA/ldmatrix helpers =================
__device__ __forceinline__ void cp16(uint32_t smem, const __half* g) {
    asm volatile("cp.async.cg.shared.global [%0], [%1], 16;\n" :: "r"(smem), "l"(g));
}

__device__ __forceinline__ void ldsm_x4(uint32_t* r, uint32_t addr) {
    asm volatile("ldmatrix.sync.aligned.m8n8.x4.shared.b16 {%0,%1,%2,%3}, [%4];"
        : "=r"(r[0]), "=r"(r[1]), "=r"(r[2]), "=r"(r[3]) : "r"(addr));
}

__device__ __forceinline__ void ldsm_x4_t(uint32_t* r, uint32_t addr) {
    asm volatile("ldmatrix.sync.aligned.m8n8.x4.trans.shared.b16 {%0,%1,%2,%3}, [%4];"
        : "=r"(r[0]), "=r"(r[1]), "=r"(r[2]), "=r"(r[3]) : "r"(addr));
}

__device__ __forceinline__ void mma_f16(float* c, const uint32_t* a,
                                        uint32_t b0, uint32_t b1)
{
    asm volatile(
        "mma.sync.aligned.m16n8k16.row.col.f32.f16.f16.f32 "
        "{%0,%1,%2,%3}, {%4,%5,%6,%7}, {%8,%9}, {%0,%1,%2,%3};\n"
        : "+f"(c[0]), "+f"(c[1]), "+f"(c[2]), "+f"(c[3])
        : "r"(a[0]), "r"(a[1]), "r"(a[2]), "r"(a[3]), "r"(b0), "r"(b1));
}

__device__ __forceinline__ uint32_t packh2(float a, float b) {
    __half2 h = __floats2half2_rn(a, b);
    return *reinterpret_cast<uint32_t*>(&h);
}

// ================= fp16 mma.sync GEMM, BK=32, ldmatrix, 3-stage ==========
#define BM 128
#define BN 128
#define BK 32
#define RS 40                      // row stride in halfs (80 B)
#define ABYTES  (BM * RS * 2)      // 10240
#define STAGEB  (2 * ABYTES)       // 20480
#define SMEM_GEMM (3 * STAGEB)     // 61440

template<int N, bool HOUT>
__device__ __forceinline__ void tgemm_body(
    const __half* __restrict__ A, const __half* __restrict__ W,
    const float* __restrict__ bias, void* Cv, int K)
{
    extern __shared__ __align__(16) char smem[];

    const int tid  = threadIdx.x;
    const int warp = tid >> 5, lane = tid & 31;
    const int g    = lane >> 2, tg = lane & 3;
    const int wm   = warp & 1;
    const int wn   = warp >> 1;
    const int m0   = blockIdx.y * BM;
    const int n0   = blockIdx.x * BN;

    const int lr = tid >> 1;
    const int hk = (tid & 1) * 16;
    const __half* Ag = A + (size_t)(m0 + lr) * K + hk;
    const __half* Wg = W + (size_t)(n0 + lr) * K + hk;

    const uint32_t sbase = (uint32_t)__cvta_generic_to_shared(smem);
    const uint32_t poff  = (lr * RS + hk) * 2;

    const int l7  = lane & 7;
    const int lb3 = (lane >> 3) & 1;
    const int lb4 = lane >> 4;
    uint32_t aoffA[4], boffB[2];
    #pragma unroll
    for (int i = 0; i < 4; i++) {
        const int row = wm * 64 + i * 16 + l7 + 8 * lb3;
        aoffA[i] = (row * RS + 8 * lb4) * 2;
    }
    #pragma unroll
    for (int p = 0; p < 2; p++) {
        const int row = wn * 32 + p * 16 + l7 + 8 * lb4;
        boffB[p] = (row * RS + 8 * lb3) * 2;
    }

    float acc[4][4][4];
    #pragma unroll
    for (int i = 0; i < 4; i++)
        #pragma unroll
        for (int j = 0; j < 4; j++)
            #pragma unroll
            for (int c = 0; c < 4; c++) acc[i][j][c] = 0.f;

    const int nt = K / BK;

    #pragma unroll
    for (int p = 0; p < 2; p++) {
        const __half* ap = Ag + (size_t)p * BK;
        const __half* wp = Wg + (size_t)p * BK;
        const uint32_t sA = sbase + p * STAGEB + poff;
        const uint32_t sB = sA + ABYTES;
        cp16(sA, ap);       cp16(sA + 16, ap + 8);
        cp16(sB, wp);       cp16(sB + 16, wp + 8);
        asm volatile("cp.async.commit_group;\n");
    }

    int stage = 0;
    int nstage = 2;

    for (int t = 0; t < nt; t++) {
        if (t < nt - 1) asm volatile("cp.async.wait_group 1;\n");
        else            asm volatile("cp.async.wait_group 0;\n");
        __syncthreads();

        if (t + 2 < nt) {
            const __half* ap = Ag + (size_t)(t + 2) * BK;
            const __half* wp = Wg + (size_t)(t + 2) * BK;
            const uint32_t sA = sbase + nstage * STAGEB + poff;
            const uint32_t sB = sA + ABYTES;
            cp16(sA, ap);       cp16(sA + 16, ap + 8);
            cp16(sB, wp);       cp16(sB + 16, wp + 8);
            asm volatile("cp.async.commit_group;\n");
        }

        const uint32_t aS = sbase + stage * STAGEB;
        const uint32_t bS = aS + ABYTES;

        #pragma unroll
        for (int s = 0; s < 2; s++) {
            const uint32_t ks = s * 32;
            uint32_t af[4][4], bfr[4][2];
            #pragma unroll
            for (int i = 0; i < 4; i++)
                ldsm_x4(af[i], aS + aoffA[i] + ks);
            #pragma unroll
            for (int p = 0; p < 2; p++) {
                uint32_t br[4];
                ldsm_x4(br, bS + boffB[p] + ks);
                bfr[2 * p][0]     = br[0];  bfr[2 * p][1]     = br[1];
                bfr[2 * p + 1][0] = br[2];  bfr[2 * p + 1][1] = br[3];
            }
            #pragma unroll
            for (int i = 0; i < 4; i++)
                #pragma unroll
                for (int j = 0; j < 4; j++)
                    mma_f16(acc[i][j], af[i], bfr[j][0], bfr[j][1]);
        }

        stage  = (stage  == 2) ? 0 : stage  + 1;
        nstage = (nstage == 2) ? 0 : nstage + 1;
    }

    #pragma unroll
    for (int i = 0; i < 4; i++) {
        const int rb = m0 + wm * 64 + i * 16 + g;
        #pragma unroll
        for (int j = 0; j < 4; j++) {
            const int cb = n0 + wn * 32 + j * 8 + 2 * tg;
            const float b0v = bias[cb], b1v = bias[cb + 1];
            if (HOUT) {
                __half* C = (__half*)Cv;
                *reinterpret_cast<__half2*>(&C[(size_t)rb * N + cb]) =
                    __floats2half2_rn(acc[i][j][0] + b0v, acc[i][j][1] + b1v);
                *reinterpret_cast<__half2*>(&C[(size_t)(rb + 8) * N + cb]) =
                    __floats2half2_rn(acc[i][j][2] + b0v, acc[i][j][3] + b1v);
            } else {
                float* C = (float*)Cv;
                float2 v0, v1;
                v0.x = acc[i][j][0] + b0v;  v0.y = acc[i][j][1] + b1v;
                v1.x = acc[i][j][2] + b0v;  v1.y = acc[i][j][3] + b1v;
                *reinterpret_cast<float2*>(&C[(size_t)rb * N + cb])       = v0;
                *reinterpret_cast<float2*>(&C[(size_t)(rb + 8) * N + cb]) = v1;
            }
        }
    }
}

__global__ __launch_bounds__(256, 2) void k_qkv(const float* __restrict__ b)
{
    tgemm_body<QKVD, true>(d_xh, d_wqh, b, d_qkv, KDIM);
}

__global__ __launch_bounds__(256, 2) void k_proj(const float* __restrict__ b,
                                                 float* __restrict__ out)
{
    tgemm_body<DIM, false>(d_att, d_wph, b, out, KDIM);
}

// ================= fp16 attention: one block per (b,h), P kept in registers
// smem (bytes): Q[64][40]h @0, K @5120, V @10240  -- 15360 total
#define AQ  0u
#define AK  5120u
#define AV  10240u
#define ATT_SMEM 15360

__global__ __launch_bounds__(128, 6) void attn_tc()
{
    __shared__ __align__(16) char smraw[ATT_SMEM];
    const uint32_t sb = (uint32_t)__cvta_generic_to_shared(smraw);

    const int b = blockIdx.x / NH;
    const int h = blockIdx.x % NH;
    const int tid = threadIdx.x;

    const __half* base = d_qkv + (size_t)b * NTOK * QKVD + h * HD;

    // zero pad rows 54..63 of Q,K,V
    for (int i = tid; i < 480; i += 128) {
        const int seg = i / 160;
        const int rr  = 54 + (i / 16) % 10;
        const int cw  = i % 16;
        reinterpret_cast<uint32_t*>(smraw)[(seg * 5120 + rr * 80) / 4 + cw] = 0;
    }
    // cp.async the 54 valid rows (q,k,v: 64 B each = 4 x 16 B)
    for (int i = tid; i < 648; i += 128) {
        const int r   = i / 12;
        const int seg = (i % 12) / 4;
        const int ch  = i % 4;
        cp16(sb + seg * 5120 + r * 80 + ch * 16,
             base + r * QKVD + seg * DIM + ch * 8);
    }
    asm volatile("cp.async.commit_group;\n");
    asm volatile("cp.async.wait_group 0;\n");
    __syncthreads();

    const int w = tid >> 5, lane = tid & 31;
    const int g = lane >> 2, tg = lane & 3;
    const int r0 = w * 16 + g;

    const int l7  = lane & 7;
    const int lb3 = (lane >> 3) & 1;
    const int lb4 = lane >> 4;

    const uint32_t aoffQ = ((w * 16 + l7 + 8 * lb3) * 40 + 8 * lb4) * 2;
    uint32_t boffK[4];
    #pragma unroll
    for (int j2 = 0; j2 < 4; j2++)
        boffK[j2] = ((j2 * 16 + l7 + 8 * lb4) * 40 + 8 * lb3) * 2;
    const int g2 = lane >> 3;
    const uint32_t voffV = (((g2 & 1) * 8 + l7) * 40 + (g2 >> 1) * 8) * 2;

    // ---- QK^T (fp16, 16 MMAs) ----
    float s[8][4];
    #pragma unroll
    for (int j = 0; j < 8; j++)
        #pragma unroll
        for (int c = 0; c < 4; c++) s[j][c] = 0.f;

    #pragma unroll
    for (int kc = 0; kc < 2; kc++) {
        const uint32_t ks = kc * 32;
        uint32_t aQ[4];
        ldsm_x4(aQ, sb + AQ + aoffQ + ks);
        #pragma unroll
        for (int j2 = 0; j2 < 4; j2++) {
            uint32_t bK[4];
            ldsm_x4(bK, sb + AK + boffK[j2] + ks);
            mma_f16(s[2 * j2],     aQ, bK[0], bK[1]);
            mma_f16(s[2 * j2 + 1], aQ, bK[2], bK[3]);
        }
    }

    // ---- scale + bias + mask ----
    const __half* bmp = d_bmh + ((size_t)(h * NWIN + (b & (NWIN - 1)))) * 64 * 64;
    #pragma unroll
    for (int j = 0; j < 8; j++) {
        const float2 t0 = __half22float2(
            *reinterpret_cast<const __half2*>(&bmp[r0 * 64 + j * 8 + 2 * tg]));
        const float2 t1 = __half22float2(
            *reinterpret_cast<const __half2*>(&bmp[(r0 + 8) * 64 + j * 8 + 2 * tg]));
        s[j][0] = s[j][0] * SCALE + t0.x;
        s[j][1] = s[j][1] * SCALE + t0.y;
        s[j][2] = s[j][2] * SCALE + t1.x;
        s[j][3] = s[j][3] * SCALE + t1.y;
    }

    // ---- softmax (rows r0 via c0/c1 with inv0; rows r0+8 via c2/c3, inv1) --
    float m0 = -1e30f, m1 = -1e30f;
    #pragma unroll
    for (int j = 0; j < 8; j++) {
        m0 = fmaxf(m0, fmaxf(s[j][0], s[j][1]));
        m1 = fmaxf(m1, fmaxf(s[j][2], s[j][3]));
    }
    m0 = fmaxf(m0, __shfl_xor_sync(0xffffffffu, m0, 1));
    m0 = fmaxf(m0, __shfl_xor_sync(0xffffffffu, m0, 2));
    m1 = fmaxf(m1, __shfl_xor_sync(0xffffffffu, m1, 1));
    m1 = fmaxf(m1, __shfl_xor_sync(0xffffffffu, m1, 2));

    float sum0 = 0.f, sum1 = 0.f;
    #pragma unroll
    for (int j = 0; j < 8; j++) {
        s[j][0] = __expf(s[j][0] - m0);
        s[j][1] = __expf(s[j][1] - m0);
        s[j][2] = __expf(s[j][2] - m1);
        s[j][3] = __expf(s[j][3] - m1);
        sum0 += s[j][0] + s[j][1];
        sum1 += s[j][2] + s[j][3];
    }
    sum0 += __shfl_xor_sync(0xffffffffu, sum0, 1);
    sum0 += __shfl_xor_sync(0xffffffffu, sum0, 2);
    sum1 += __shfl_xor_sync(0xffffffffu, sum1, 1);
    sum1 += __shfl_xor_sync(0xffffffffu, sum1, 2);
    const float inv0 = 1.f / sum0;
    const float inv1 = 1.f / sum1;

    // ---- PV: P fragments built directly from s (no smem round-trip) ----
    // A-fragment of P k-tile kc: a0 = P[g][16kc+2tg..], a1 = P[g+8][..],
    // a2 = P[g][16kc+8+2tg..], a3 = P[g+8][..]; exactly s[2kc], s[2kc+1].
    float o[4][4];
    #pragma unroll
    for (int n = 0; n < 4; n++)
        #pragma unroll
        for (int c = 0; c < 4; c++) o[n][c] = 0.f;

    #pragma unroll
    for (int kc = 0; kc < 4; kc++) {
        uint32_t aP[4];
        aP[0] = packh2(s[2 * kc][0] * inv0,     s[2 * kc][1] * inv0);
        aP[1] = packh2(s[2 * kc][2] * inv1,     s[2 * kc][3] * inv1);
        aP[2] = packh2(s[2 * kc + 1][0] * inv0, s[2 * kc + 1][1] * inv0);
        aP[3] = packh2(s[2 * kc + 1][2] * inv1, s[2 * kc + 1][3] * inv1);
        #pragma unroll
        for (int nh = 0; nh < 2; nh++) {
            uint32_t bV[4];
            ldsm_x4_t(bV, sb + AV + voffV + nh * 32 + kc * 1280);
            mma_f16(o[2 * nh],     aP, bV[0], bV[1]);
            mma_f16(o[2 * nh + 1], aP, bV[2], bV[3]);
        }
    }

    // ---- store fp16 for the proj GEMM ----
    if (r0 < NTOK) {
        __half* op = d_att + ((size_t)b * NTOK + r0) * DIM + h * HD;
        #pragma unroll
        for (int n = 0; n < 4; n++)
            *reinterpret_cast<__half2*>(&op[n * 8 + 2 * tg]) =
                __floats2half2_rn(o[n][0], o[n][1]);
    }
    if (r0 + 8 < NTOK) {
        __half* op = d_att + ((size_t)b * NTOK + r0 + 8) * DIM + h * HD;
        #pragma unroll
        for (int n = 0; n < 4; n++)
            *reinterpret_cast<__half2*>(&op[n * 8 + 2 * tg]) =
                __floats2half2_rn(o[n][2], o[n][3]);
    }
}

// ---------------- launch ----------------
extern "C" void kernel_launch(void* const* d_in, const int* in_sizes, int n_in,
                              void* d_out, int out_size)
{
    const float* x      = (const float*)d_in[0];
    const float* mask   = (const float*)d_in[1];
    const float* qkv_w  = (const float*)d_in[2];
    const float* qkv_b  = (const float*)d_in[3];
    const float* proj_w = (const float*)d_in[4];
    const float* proj_b = (const float*)d_in[5];
    const float* rpb    = (const float*)d_in[6];
    float* out          = (float*)d_out;

    cudaFuncSetAttribute(k_qkv,  cudaFuncAttributeMaxDynamicSharedMemorySize, SMEM_GEMM);
    cudaFuncSetAttribute(k_proj, cudaFuncAttributeMaxDynamicSharedMemorySize, SMEM_GEMM);

    {
        const int total = PN1 + PN2 + PN3;
        prep_all<<<(total + 255) / 256, 256>>>(x, qkv_w, proj_w);
        bm_kernel<<<(NWIN * 64 * 64 + 255) / 256, 256>>>(rpb, mask);
    }

    {   // QKV: (55296 x 384) @ (1152 x 384)^T -> fp16
        dim3 grid(QKVD / BN, MTOK / BM);
        k_qkv<<<grid, 256, SMEM_GEMM>>>(qkv_b);
    }

    attn_tc<<<B_ * NH, 128>>>();

    {   // proj: (55296 x 384) @ (384 x 384)^T -> fp32 out
        dim3 grid(DIM / BN, MTOK / BM);
        k_proj<<<grid, 256, SMEM_GEMM>>>(proj_b, out);
    }
}